// round 6
// baseline (speedup 1.0000x reference)
#include <cuda_runtime.h>
#include <cstdint>

// ---------------------------------------------------------------------------
// GNBlock: h = BN(PReLU(segment_sum(relu(x[src]@W1+b1)@W2+b2, dst) + x@W_root + b_root))
// N=50000, E=800000, C_IN=64, C_HID=128, C_OUT=64
//
// Pipeline:
//   setup: zero agg/cnt/stats, detect index dtype
//   hist + scan + reorder: counting-sort edges by src into 128-node tiles
//   fused: per 128-node tile compute msg MLP (+ root GEMM -> g_h), then
//          scatter msg from SMEM via red.global.add.v4 into g_agg
//   stats/bn: h = g_h + g_agg, PReLU, batch-norm -> out
// ---------------------------------------------------------------------------

#define N_MAX 50000
#define E_MAX 800000
#define C_IN 64
#define C_HID 128
#define C_OUT 64
#define TILE_N 128
#define MT 512
#define NT 256
#define SCAN_B 256
#define NBLK_SCAN ((N_MAX + SCAN_B - 1) / SCAN_B)  // 196

__device__ __align__(16) float g_h[N_MAX * C_OUT];    // root transform
__device__ __align__(16) float g_agg[N_MAX * C_OUT];  // edge aggregation
__device__ float g_stats[2 * C_OUT];
__device__ int g_idx64;
__device__ int g_cnt[N_MAX];
__device__ int g_off[N_MAX + 1];
__device__ int g_cursor[N_MAX];
__device__ int g_epk[E_MAX];   // packed: dst*128 + (src&127)
__device__ int g_part[SCAN_B];
__device__ int g_pscan[SCAN_B];

// ---- f32x2 packed helpers ---------------------------------------------------
__device__ __forceinline__ unsigned long long pack2(float v) {
    unsigned long long r;
    unsigned int u = __float_as_uint(v);
    asm("mov.b64 %0, {%1, %2};" : "=l"(r) : "r"(u), "r"(u));
    return r;
}
__device__ __forceinline__ unsigned long long fma2(unsigned long long a,
                                                   unsigned long long b,
                                                   unsigned long long c) {
    unsigned long long d;
    asm("fma.rn.f32x2 %0, %1, %2, %3;" : "=l"(d) : "l"(a), "l"(b), "l"(c));
    return d;
}
__device__ __forceinline__ float2 unpack2(unsigned long long v) {
    unsigned int lo, hi;
    asm("mov.b64 {%0, %1}, %2;" : "=r"(lo), "=r"(hi) : "l"(v));
    float2 f;
    f.x = __uint_as_float(lo);
    f.y = __uint_as_float(hi);
    return f;
}
__device__ __forceinline__ void load_edge(const void* ei, int E, int e, int& s, int& d) {
    if (g_idx64) {
        const long long* p = (const long long*)ei;
        s = (int)__ldg(&p[e]);
        d = (int)__ldg(&p[E + e]);
    } else {
        const int* p = (const int*)ei;
        s = __ldg(&p[e]);
        d = __ldg(&p[E + e]);
    }
}

// ---------------------------------------------------------------------------
// K0: zero g_agg / g_cnt / g_stats + detect index width (block 0)
// ---------------------------------------------------------------------------
__global__ void setup_kernel(const void* __restrict__ ei, int N) {
    int gid = blockIdx.x * blockDim.x + threadIdx.x;
    int stride = gridDim.x * blockDim.x;
    float4* a4 = reinterpret_cast<float4*>(g_agg);
    for (int i = gid; i < N * (C_OUT / 4); i += stride) a4[i] = make_float4(0, 0, 0, 0);
    for (int i = gid; i < N; i += stride) g_cnt[i] = 0;
    if (gid < 128) g_stats[gid] = 0.f;
    if (blockIdx.x == 0 && threadIdx.x < 32) {
        const long long* p = (const long long*)ei;
        long long v = p[threadIdx.x];
        unsigned ok = __ballot_sync(0xffffffffu, v >= 0 && v < (long long)N);
        if (threadIdx.x == 0) g_idx64 = (ok == 0xffffffffu) ? 1 : 0;
    }
}

// ---------------------------------------------------------------------------
// K1: histogram of src
// ---------------------------------------------------------------------------
__global__ void hist_kernel(const void* __restrict__ ei, int E) {
    int e = blockIdx.x * blockDim.x + threadIdx.x;
    if (e >= E) return;
    int s, d;
    load_edge(ei, E, e, s, d);
    atomicAdd(&g_cnt[s], 1);
}

// ---------------------------------------------------------------------------
// K2a/b/c: 3-phase exclusive scan of g_cnt -> g_off (+ g_cursor copy)
// ---------------------------------------------------------------------------
__global__ void scanA_kernel(int N) {
    __shared__ int ss[SCAN_B];
    int t = threadIdx.x;
    int i = blockIdx.x * SCAN_B + t;
    ss[t] = (i < N) ? g_cnt[i] : 0;
    __syncthreads();
    for (int o = SCAN_B / 2; o > 0; o >>= 1) {
        if (t < o) ss[t] += ss[t + o];
        __syncthreads();
    }
    if (t == 0) g_part[blockIdx.x] = ss[0];
}

__global__ void scanB_kernel(int nb) {
    __shared__ int ss[SCAN_B];
    int t = threadIdx.x;
    int v = (t < nb) ? g_part[t] : 0;
    ss[t] = v;
    __syncthreads();
    for (int o = 1; o < SCAN_B; o <<= 1) {
        int xv = (t >= o) ? ss[t - o] : 0;
        __syncthreads();
        ss[t] += xv;
        __syncthreads();
    }
    g_pscan[t] = ss[t] - v;  // exclusive
}

__global__ void scanC_kernel(int N) {
    __shared__ int ss[SCAN_B];
    int t = threadIdx.x;
    int i = blockIdx.x * SCAN_B + t;
    int v = (i < N) ? g_cnt[i] : 0;
    ss[t] = v;
    __syncthreads();
    for (int o = 1; o < SCAN_B; o <<= 1) {
        int xv = (t >= o) ? ss[t - o] : 0;
        __syncthreads();
        ss[t] += xv;
        __syncthreads();
    }
    int off = g_pscan[blockIdx.x] + ss[t] - v;  // exclusive global
    if (i < N) {
        g_off[i] = off;
        g_cursor[i] = off;
        if (i == N - 1) g_off[N] = off + v;
    }
}

// ---------------------------------------------------------------------------
// K3: reorder edges into src-sorted order, packed as dst*128 + (src % 128)
// ---------------------------------------------------------------------------
__global__ void reorder_kernel(const void* __restrict__ ei, int E) {
    int e = blockIdx.x * blockDim.x + threadIdx.x;
    if (e >= E) return;
    int s, d;
    load_edge(ei, E, e, s, d);
    int pos = atomicAdd(&g_cursor[s], 1);
    g_epk[pos] = (d << 7) | (s & 127);
}

// ---------------------------------------------------------------------------
// K4: fused per-tile kernel (128 nodes, 512 threads):
//   GEMM1: sH = relu(sX@W1+b1)      GEMM3: g_h = sX@Wr+br
//   GEMM2: msg = sH@W2+b2 -> stored back into sX (as sMsg)
//   edge loop: red.global.add msg quads from SMEM into g_agg[dst]
// ---------------------------------------------------------------------------
#define SX_PITCH 68
#define SH_PITCH 132
#define SMEM_FLOATS (8192 + 8192 + 4096 + TILE_N * SX_PITCH + TILE_N * SH_PITCH + 256)
#define SMEM_BYTES (SMEM_FLOATS * 4)

__global__ __launch_bounds__(MT) void fused_kernel(
    const float* __restrict__ x, const float* __restrict__ W1,
    const float* __restrict__ b1, const float* __restrict__ W2,
    const float* __restrict__ b2, const float* __restrict__ Wr,
    const float* __restrict__ br, int N) {
    extern __shared__ float sm[];
    float* sW1 = sm;                      // 64 x 128
    float* sW2 = sW1 + 64 * 128;          // 128 x 64
    float* sWr = sW2 + 128 * 64;          // 64 x 64
    float* sX = sWr + 64 * 64;            // 128 x 68 (doubles as sMsg)
    float* sH = sX + TILE_N * SX_PITCH;   // 128 x 132
    float* sb1 = sH + TILE_N * SH_PITCH;  // 128
    float* sb2 = sb1 + 128;               // 64
    float* sbr = sb2 + 64;                // 64

    const int tid = threadIdx.x;
    const int n0 = blockIdx.x * TILE_N;

    for (int i = tid; i < 2048; i += MT)
        reinterpret_cast<float4*>(sW1)[i] = reinterpret_cast<const float4*>(W1)[i];
    for (int i = tid; i < 2048; i += MT)
        reinterpret_cast<float4*>(sW2)[i] = reinterpret_cast<const float4*>(W2)[i];
    for (int i = tid; i < 1024; i += MT)
        reinterpret_cast<float4*>(sWr)[i] = reinterpret_cast<const float4*>(Wr)[i];
    if (tid < 128) sb1[tid] = b1[tid];
    else if (tid < 192) sb2[tid - 128] = b2[tid - 128];
    else if (tid < 256) sbr[tid - 192] = br[tid - 192];

    for (int i = tid; i < TILE_N * 16; i += MT) {
        int r = i >> 4, q = i & 15;
        int n = n0 + r;
        if (n >= N) n = N - 1;
        float4 v = reinterpret_cast<const float4*>(x + (long long)n * C_IN)[q];
        *reinterpret_cast<float4*>(&sX[r * SX_PITCH + q * 4]) = v;
    }
    __syncthreads();

    const int hg = tid & 15;
    const int rg = tid >> 4;
    const int hb = hg * 8;
    const int kb = hg * 4;
    const int rb = rg * 4;

    // ---- GEMM1 ----
    {
        unsigned long long acc[4][4];
#pragma unroll
        for (int e = 0; e < 4; e++)
#pragma unroll
            for (int p = 0; p < 4; p++) acc[e][p] = 0ULL;

#pragma unroll 8
        for (int k = 0; k < C_IN; k += 2) {
            ulonglong2 wa0 = *reinterpret_cast<const ulonglong2*>(&sW1[k * C_HID + hb]);
            ulonglong2 wa1 = *reinterpret_cast<const ulonglong2*>(&sW1[k * C_HID + hb + 4]);
            ulonglong2 wb0 = *reinterpret_cast<const ulonglong2*>(&sW1[(k + 1) * C_HID + hb]);
            ulonglong2 wb1 = *reinterpret_cast<const ulonglong2*>(&sW1[(k + 1) * C_HID + hb + 4]);
#pragma unroll
            for (int e = 0; e < 4; e++) {
                float2 xv = *reinterpret_cast<const float2*>(&sX[(rb + e) * SX_PITCH + k]);
                unsigned long long x0 = pack2(xv.x), x1 = pack2(xv.y);
                acc[e][0] = fma2(x0, wa0.x, acc[e][0]);
                acc[e][1] = fma2(x0, wa0.y, acc[e][1]);
                acc[e][2] = fma2(x0, wa1.x, acc[e][2]);
                acc[e][3] = fma2(x0, wa1.y, acc[e][3]);
                acc[e][0] = fma2(x1, wb0.x, acc[e][0]);
                acc[e][1] = fma2(x1, wb0.y, acc[e][1]);
                acc[e][2] = fma2(x1, wb1.x, acc[e][2]);
                acc[e][3] = fma2(x1, wb1.y, acc[e][3]);
            }
        }
#pragma unroll
        for (int e = 0; e < 4; e++) {
#pragma unroll
            for (int p = 0; p < 4; p++) {
                float2 v = unpack2(acc[e][p]);
                v.x = fmaxf(v.x + sb1[hb + 2 * p], 0.f);
                v.y = fmaxf(v.y + sb1[hb + 2 * p + 1], 0.f);
                *reinterpret_cast<float2*>(&sH[(rb + e) * SH_PITCH + hb + 2 * p]) = v;
            }
        }
    }

    // ---- GEMM3 (reads sX only; writes g_h) ----
    {
        unsigned long long a3[4][2];
#pragma unroll
        for (int e = 0; e < 4; e++) { a3[e][0] = 0ULL; a3[e][1] = 0ULL; }

#pragma unroll 8
        for (int k = 0; k < C_IN; k += 2) {
            ulonglong2 wa = *reinterpret_cast<const ulonglong2*>(&sWr[k * C_OUT + kb]);
            ulonglong2 wb = *reinterpret_cast<const ulonglong2*>(&sWr[(k + 1) * C_OUT + kb]);
#pragma unroll
            for (int e = 0; e < 4; e++) {
                float2 xv = *reinterpret_cast<const float2*>(&sX[(rb + e) * SX_PITCH + k]);
                unsigned long long x0 = pack2(xv.x), x1 = pack2(xv.y);
                a3[e][0] = fma2(x0, wa.x, a3[e][0]);
                a3[e][1] = fma2(x0, wa.y, a3[e][1]);
                a3[e][0] = fma2(x1, wb.x, a3[e][0]);
                a3[e][1] = fma2(x1, wb.y, a3[e][1]);
            }
        }
        float c0 = sbr[kb], c1 = sbr[kb + 1], c2 = sbr[kb + 2], c3 = sbr[kb + 3];
#pragma unroll
        for (int e = 0; e < 4; e++) {
            int n = n0 + rb + e;
            if (n >= N) continue;
            float2 v0 = unpack2(a3[e][0]);
            float2 v1 = unpack2(a3[e][1]);
            float4 r;
            r.x = v0.x + c0; r.y = v0.y + c1; r.z = v1.x + c2; r.w = v1.y + c3;
            *reinterpret_cast<float4*>(&g_h[(long long)n * C_OUT + kb]) = r;
        }
    }
    __syncthreads();  // everyone done with sX; sH complete

    // ---- GEMM2: msg = sH @ W2 + b2 -> write into sX (sMsg) ----
    {
        unsigned long long a2[4][2];
#pragma unroll
        for (int e = 0; e < 4; e++) { a2[e][0] = 0ULL; a2[e][1] = 0ULL; }

#pragma unroll 8
        for (int j = 0; j < C_HID; j += 2) {
            ulonglong2 wa = *reinterpret_cast<const ulonglong2*>(&sW2[j * C_OUT + kb]);
            ulonglong2 wb = *reinterpret_cast<const ulonglong2*>(&sW2[(j + 1) * C_OUT + kb]);
#pragma unroll
            for (int e = 0; e < 4; e++) {
                float2 hv = *reinterpret_cast<const float2*>(&sH[(rb + e) * SH_PITCH + j]);
                unsigned long long h0 = pack2(hv.x), h1 = pack2(hv.y);
                a2[e][0] = fma2(h0, wa.x, a2[e][0]);
                a2[e][1] = fma2(h0, wa.y, a2[e][1]);
                a2[e][0] = fma2(h1, wb.x, a2[e][0]);
                a2[e][1] = fma2(h1, wb.y, a2[e][1]);
            }
        }
        float c0 = sb2[kb], c1 = sb2[kb + 1], c2 = sb2[kb + 2], c3 = sb2[kb + 3];
#pragma unroll
        for (int e = 0; e < 4; e++) {
            float2 v0 = unpack2(a2[e][0]);
            float2 v1 = unpack2(a2[e][1]);
            float4 r;
            r.x = v0.x + c0; r.y = v0.y + c1; r.z = v1.x + c2; r.w = v1.y + c3;
            *reinterpret_cast<float4*>(&sX[(rb + e) * SX_PITCH + kb]) = r;
        }
    }
    __syncthreads();  // sMsg ready

    // ---- edge scatter from SMEM: 16 threads per edge ----
    {
        int nEnd = n0 + TILE_N;
        if (nEnd > N) nEnd = N;
        int eBeg = __ldg(&g_off[n0]);
        int eEnd = __ldg(&g_off[nEnd]);
        const int grp = tid >> 4;   // 0..31
        const int q = tid & 15;
        for (int e = eBeg + grp; e < eEnd; e += 32) {
            int pk = __ldg(&g_epk[e]);
            int d = pk >> 7;
            int l = pk & 127;
            float4 v = *reinterpret_cast<const float4*>(&sX[l * SX_PITCH + q * 4]);
            float* pd = &g_agg[(long long)d * C_OUT + q * 4];
            asm volatile("red.global.add.v4.f32 [%0], {%1,%2,%3,%4};"
                         :: "l"(pd), "f"(v.x), "f"(v.y), "f"(v.z), "f"(v.w)
                         : "memory");
        }
    }
}

// ---------------------------------------------------------------------------
// K5: stats pass — per-channel sum/sumsq of PReLU(g_h + g_agg)  (read-only)
// ---------------------------------------------------------------------------
__global__ void prelu_stats_kernel(const float* __restrict__ prelu_w, int N) {
    const float a = prelu_w[0];
    const int total4 = N * (C_OUT / 4);
    const int stride = gridDim.x * blockDim.x;
    const float4* gh4 = reinterpret_cast<const float4*>(g_h);
    const float4* ga4 = reinterpret_cast<const float4*>(g_agg);
    float s0 = 0.f, s1 = 0.f, s2 = 0.f, s3 = 0.f;
    float q0 = 0.f, q1 = 0.f, q2 = 0.f, q3 = 0.f;
    for (int i = blockIdx.x * blockDim.x + threadIdx.x; i < total4; i += stride) {
        float4 v = gh4[i];
        float4 w = ga4[i];
        v.x += w.x; v.y += w.y; v.z += w.z; v.w += w.w;
        v.x = (v.x >= 0.f) ? v.x : a * v.x;
        v.y = (v.y >= 0.f) ? v.y : a * v.y;
        v.z = (v.z >= 0.f) ? v.z : a * v.z;
        v.w = (v.w >= 0.f) ? v.w : a * v.w;
        s0 += v.x; s1 += v.y; s2 += v.z; s3 += v.w;
        q0 += v.x * v.x; q1 += v.y * v.y; q2 += v.z * v.z; q3 += v.w * v.w;
    }
    __shared__ float rs[NT * 4], rq[NT * 4];
    int t = threadIdx.x;
    rs[t * 4 + 0] = s0; rs[t * 4 + 1] = s1; rs[t * 4 + 2] = s2; rs[t * 4 + 3] = s3;
    rq[t * 4 + 0] = q0; rq[t * 4 + 1] = q1; rq[t * 4 + 2] = q2; rq[t * 4 + 3] = q3;
    __syncthreads();
    if (t < 64) {
        int qq = t >> 2, comp = t & 3;
        float ts = 0.f, tq = 0.f;
#pragma unroll
        for (int m = 0; m < 16; m++) {
            int src = (m * 16 + qq) * 4 + comp;
            ts += rs[src];
            tq += rq[src];
        }
        atomicAdd(&g_stats[t], ts);
        atomicAdd(&g_stats[64 + t], tq);
    }
}

// ---------------------------------------------------------------------------
// K6: finalize — h = g_h + g_agg, PReLU, BN normalize, write out
// ---------------------------------------------------------------------------
__global__ void bn_kernel(float* __restrict__ out, const float* __restrict__ gamma,
                          const float* __restrict__ beta,
                          const float* __restrict__ prelu_w, int N) {
    __shared__ float sscale[C_OUT], sshift[C_OUT];
    if (threadIdx.x < C_OUT) {
        float invN = 1.f / (float)N;
        float mu = g_stats[threadIdx.x] * invN;
        float var = g_stats[64 + threadIdx.x] * invN - mu * mu;
        float inv = rsqrtf(var + 1e-5f);
        float g = gamma[threadIdx.x] * inv;
        sscale[threadIdx.x] = g;
        sshift[threadIdx.x] = beta[threadIdx.x] - mu * g;
    }
    __syncthreads();
    const float a = prelu_w[0];
    const int total4 = N * (C_OUT / 4);
    const int stride = gridDim.x * blockDim.x;
    const float4* gh4 = reinterpret_cast<const float4*>(g_h);
    const float4* ga4 = reinterpret_cast<const float4*>(g_agg);
    float4* o4 = reinterpret_cast<float4*>(out);
    for (int i = blockIdx.x * blockDim.x + threadIdx.x; i < total4; i += stride) {
        int q = (i & 15);
        float4 sc = reinterpret_cast<const float4*>(sscale)[q];
        float4 sh = reinterpret_cast<const float4*>(sshift)[q];
        float4 v = gh4[i];
        float4 w = ga4[i];
        v.x += w.x; v.y += w.y; v.z += w.z; v.w += w.w;
        v.x = (v.x >= 0.f) ? v.x : a * v.x;
        v.y = (v.y >= 0.f) ? v.y : a * v.y;
        v.z = (v.z >= 0.f) ? v.z : a * v.z;
        v.w = (v.w >= 0.f) ? v.w : a * v.w;
        float4 r;
        r.x = fmaf(v.x, sc.x, sh.x);
        r.y = fmaf(v.y, sc.y, sh.y);
        r.z = fmaf(v.z, sc.z, sh.z);
        r.w = fmaf(v.w, sc.w, sh.w);
        o4[i] = r;
    }
}

// ---------------------------------------------------------------------------
extern "C" void kernel_launch(void* const* d_in, const int* in_sizes, int n_in,
                              void* d_out, int out_size) {
    const float* x = (const float*)d_in[0];
    const void* ei = d_in[1];
    const float* W1 = (const float*)d_in[2];
    const float* b1 = (const float*)d_in[3];
    const float* W2 = (const float*)d_in[4];
    const float* b2 = (const float*)d_in[5];
    const float* Wr = (const float*)d_in[6];
    const float* br = (const float*)d_in[7];
    const float* pw = (const float*)d_in[8];
    const float* gamma = (const float*)d_in[9];
    const float* beta = (const float*)d_in[10];
    float* out = (float*)d_out;

    const int N = in_sizes[0] / C_IN;
    const int E = in_sizes[1] / 2;
    const int nScanBlk = (N + SCAN_B - 1) / SCAN_B;

    cudaFuncSetAttribute(fused_kernel, cudaFuncAttributeMaxDynamicSharedMemorySize,
                         SMEM_BYTES);

    // setup: zero agg/cnt/stats + dtype probe
    setup_kernel<<<1600, 512>>>(ei, N);
    // counting sort by src
    hist_kernel<<<(E + NT - 1) / NT, NT>>>(ei, E);
    scanA_kernel<<<nScanBlk, SCAN_B>>>(N);
    scanB_kernel<<<1, SCAN_B>>>(nScanBlk);
    scanC_kernel<<<nScanBlk, SCAN_B>>>(N);
    reorder_kernel<<<(E + NT - 1) / NT, NT>>>(ei, E);
    // fused MLP + root + smem scatter
    const int numTiles = (N + TILE_N - 1) / TILE_N;
    fused_kernel<<<numTiles, MT, SMEM_BYTES>>>(x, W1, b1, W2, b2, Wr, br, N);
    // epilogue
    prelu_stats_kernel<<<592, NT>>>(pw, N);
    bn_kernel<<<592, NT>>>(out, gamma, beta, pw, N);
}

// round 7
// speedup vs baseline: 1.0754x; 1.0754x over previous
#include <cuda_runtime.h>
#include <cstdint>

// ---------------------------------------------------------------------------
// GNBlock: h = BN(PReLU(segment_sum(relu(x[src]@W1+b1)@W2+b2, dst) + x@W_root + b_root))
// N=50000, E=800000, C_IN=64, C_HID=128, C_OUT=64
//
// msg = MLP(x[src]) is per-node -> compute once per node.
// Aggregation by GATHER: counting-sort edges by dst (CSR), then each dst
// group reads its msg rows from L2 and writes ONE row (no atomics, half the
// L2 traffic of scatter). PReLU + BN-stats fused into the gather kernel.
// ---------------------------------------------------------------------------

#define N_MAX 50000
#define E_MAX 800000
#define C_IN 64
#define C_HID 128
#define C_OUT 64
#define TILE_N 128
#define MT 512
#define NT 256
#define SCAN_B 256

__device__ __align__(16) float g_h[N_MAX * C_OUT];    // root -> post-PReLU h
__device__ __align__(16) float g_msg[N_MAX * C_OUT];  // per-node messages
__device__ float g_stats[2 * C_OUT];
__device__ int g_idx64;
__device__ int g_cnt[N_MAX];
__device__ int g_off[N_MAX + 1];
__device__ int g_cursor[N_MAX];
__device__ int g_esrc[E_MAX];  // src list, CSR-ordered by dst
__device__ int g_part[SCAN_B];

// ---- f32x2 packed helpers ---------------------------------------------------
__device__ __forceinline__ unsigned long long pack2(float v) {
    unsigned long long r;
    unsigned int u = __float_as_uint(v);
    asm("mov.b64 %0, {%1, %2};" : "=l"(r) : "r"(u), "r"(u));
    return r;
}
__device__ __forceinline__ unsigned long long fma2(unsigned long long a,
                                                   unsigned long long b,
                                                   unsigned long long c) {
    unsigned long long d;
    asm("fma.rn.f32x2 %0, %1, %2, %3;" : "=l"(d) : "l"(a), "l"(b), "l"(c));
    return d;
}
__device__ __forceinline__ float2 unpack2(unsigned long long v) {
    unsigned int lo, hi;
    asm("mov.b64 {%0, %1}, %2;" : "=r"(lo), "=r"(hi) : "l"(v));
    float2 f;
    f.x = __uint_as_float(lo);
    f.y = __uint_as_float(hi);
    return f;
}

// ---------------------------------------------------------------------------
// K0: zero g_cnt/g_stats + detect index width
// ---------------------------------------------------------------------------
__global__ void setup_kernel(const void* __restrict__ ei, int N) {
    int gid = blockIdx.x * blockDim.x + threadIdx.x;
    int stride = gridDim.x * blockDim.x;
    for (int i = gid; i < N; i += stride) g_cnt[i] = 0;
    if (gid < 128) g_stats[gid] = 0.f;
    if (blockIdx.x == 0 && threadIdx.x < 32) {
        const long long* p = (const long long*)ei;
        long long v = p[threadIdx.x];
        unsigned ok = __ballot_sync(0xffffffffu, v >= 0 && v < (long long)N);
        if (threadIdx.x == 0) g_idx64 = (ok == 0xffffffffu) ? 1 : 0;
    }
}

// ---------------------------------------------------------------------------
// K1: histogram of dst (loads dst column only)
// ---------------------------------------------------------------------------
__global__ void hist_kernel(const void* __restrict__ ei, int E) {
    int e = blockIdx.x * blockDim.x + threadIdx.x;
    if (e >= E) return;
    int d;
    if (g_idx64) d = (int)__ldg(&((const long long*)ei)[E + e]);
    else d = __ldg(&((const int*)ei)[E + e]);
    atomicAdd(&g_cnt[d], 1);
}

// ---------------------------------------------------------------------------
// K2a: per-block partial sums of g_cnt
// ---------------------------------------------------------------------------
__global__ void scanA_kernel(int N) {
    __shared__ int ss[SCAN_B];
    int t = threadIdx.x;
    int i = blockIdx.x * SCAN_B + t;
    ss[t] = (i < N) ? g_cnt[i] : 0;
    __syncthreads();
    for (int o = SCAN_B / 2; o > 0; o >>= 1) {
        if (t < o) ss[t] += ss[t + o];
        __syncthreads();
    }
    if (t == 0) g_part[blockIdx.x] = ss[0];
}

// ---------------------------------------------------------------------------
// K2b: per-block scan; block prefix computed inline by reducing g_part[0..b)
// (196 partials, L2-resident — no serial scanB kernel needed)
// ---------------------------------------------------------------------------
__global__ void scanC_kernel(int N) {
    __shared__ int ss[SCAN_B];
    __shared__ int sp[SCAN_B];
    int t = threadIdx.x;
    int b = blockIdx.x;
    int i = b * SCAN_B + t;
    int v = (i < N) ? g_cnt[i] : 0;
    ss[t] = v;
    sp[t] = (t < b) ? g_part[t] : 0;  // nb <= 256 (N <= 50000)
    __syncthreads();
    for (int o = SCAN_B / 2; o > 0; o >>= 1) {
        if (t < o) sp[t] += sp[t + o];
        __syncthreads();
    }
    int prefix = sp[0];
    // inclusive scan of ss
    for (int o = 1; o < SCAN_B; o <<= 1) {
        int xv = (t >= o) ? ss[t - o] : 0;
        __syncthreads();
        ss[t] += xv;
        __syncthreads();
    }
    int off = prefix + ss[t] - v;  // exclusive
    if (i < N) {
        g_off[i] = off;
        g_cursor[i] = off;
        if (i == N - 1) g_off[N] = off + v;
    }
}

// ---------------------------------------------------------------------------
// K3: bucket edges by dst: g_esrc[pos] = src
// ---------------------------------------------------------------------------
__global__ void reorder_kernel(const void* __restrict__ ei, int E) {
    int e = blockIdx.x * blockDim.x + threadIdx.x;
    if (e >= E) return;
    int s, d;
    if (g_idx64) {
        const long long* p = (const long long*)ei;
        s = (int)__ldg(&p[e]);
        d = (int)__ldg(&p[E + e]);
    } else {
        const int* p = (const int*)ei;
        s = __ldg(&p[e]);
        d = __ldg(&p[E + e]);
    }
    int pos = atomicAdd(&g_cursor[d], 1);
    g_esrc[pos] = s;
}

// ---------------------------------------------------------------------------
// K4: fused per-node kernel (tile of 128 nodes, 512 threads):
//   msg[n] = relu(x[n]@W1 + b1) @ W2 + b2  -> g_msg
//   h[n]   = x[n]@W_root + b_root          -> g_h
// ---------------------------------------------------------------------------
#define SX_PITCH 68
#define SH_PITCH 132
#define SMEM_FLOATS (8192 + 8192 + 4096 + TILE_N * SX_PITCH + TILE_N * SH_PITCH + 256)
#define SMEM_BYTES (SMEM_FLOATS * 4)

__global__ __launch_bounds__(MT) void msg_kernel(
    const float* __restrict__ x, const float* __restrict__ W1,
    const float* __restrict__ b1, const float* __restrict__ W2,
    const float* __restrict__ b2, const float* __restrict__ Wr,
    const float* __restrict__ br, int N) {
    extern __shared__ float sm[];
    float* sW1 = sm;                      // 64 x 128
    float* sW2 = sW1 + 64 * 128;          // 128 x 64
    float* sWr = sW2 + 128 * 64;          // 64 x 64
    float* sX = sWr + 64 * 64;            // 128 x 68 (padded)
    float* sH = sX + TILE_N * SX_PITCH;   // 128 x 132 (padded)
    float* sb1 = sH + TILE_N * SH_PITCH;  // 128
    float* sb2 = sb1 + 128;               // 64
    float* sbr = sb2 + 64;                // 64

    const int tid = threadIdx.x;
    const int n0 = blockIdx.x * TILE_N;

    for (int i = tid; i < 2048; i += MT)
        reinterpret_cast<float4*>(sW1)[i] = reinterpret_cast<const float4*>(W1)[i];
    for (int i = tid; i < 2048; i += MT)
        reinterpret_cast<float4*>(sW2)[i] = reinterpret_cast<const float4*>(W2)[i];
    for (int i = tid; i < 1024; i += MT)
        reinterpret_cast<float4*>(sWr)[i] = reinterpret_cast<const float4*>(Wr)[i];
    if (tid < 128) sb1[tid] = b1[tid];
    else if (tid < 192) sb2[tid - 128] = b2[tid - 128];
    else if (tid < 256) sbr[tid - 192] = br[tid - 192];

    for (int i = tid; i < TILE_N * 16; i += MT) {
        int r = i >> 4, q = i & 15;
        int n = n0 + r;
        if (n >= N) n = N - 1;
        float4 v = reinterpret_cast<const float4*>(x + (long long)n * C_IN)[q];
        *reinterpret_cast<float4*>(&sX[r * SX_PITCH + q * 4]) = v;
    }
    __syncthreads();

    const int hg = tid & 15;
    const int rg = tid >> 4;
    const int hb = hg * 8;
    const int kb = hg * 4;
    const int rb = rg * 4;

    // ---- GEMM1: sH = relu(sX @ W1 + b1) ----
    {
        unsigned long long acc[4][4];
#pragma unroll
        for (int e = 0; e < 4; e++)
#pragma unroll
            for (int p = 0; p < 4; p++) acc[e][p] = 0ULL;

#pragma unroll 8
        for (int k = 0; k < C_IN; k += 2) {
            ulonglong2 wa0 = *reinterpret_cast<const ulonglong2*>(&sW1[k * C_HID + hb]);
            ulonglong2 wa1 = *reinterpret_cast<const ulonglong2*>(&sW1[k * C_HID + hb + 4]);
            ulonglong2 wb0 = *reinterpret_cast<const ulonglong2*>(&sW1[(k + 1) * C_HID + hb]);
            ulonglong2 wb1 = *reinterpret_cast<const ulonglong2*>(&sW1[(k + 1) * C_HID + hb + 4]);
#pragma unroll
            for (int e = 0; e < 4; e++) {
                float2 xv = *reinterpret_cast<const float2*>(&sX[(rb + e) * SX_PITCH + k]);
                unsigned long long x0 = pack2(xv.x), x1 = pack2(xv.y);
                acc[e][0] = fma2(x0, wa0.x, acc[e][0]);
                acc[e][1] = fma2(x0, wa0.y, acc[e][1]);
                acc[e][2] = fma2(x0, wa1.x, acc[e][2]);
                acc[e][3] = fma2(x0, wa1.y, acc[e][3]);
                acc[e][0] = fma2(x1, wb0.x, acc[e][0]);
                acc[e][1] = fma2(x1, wb0.y, acc[e][1]);
                acc[e][2] = fma2(x1, wb1.x, acc[e][2]);
                acc[e][3] = fma2(x1, wb1.y, acc[e][3]);
            }
        }
#pragma unroll
        for (int e = 0; e < 4; e++) {
#pragma unroll
            for (int p = 0; p < 4; p++) {
                float2 v = unpack2(acc[e][p]);
                v.x = fmaxf(v.x + sb1[hb + 2 * p], 0.f);
                v.y = fmaxf(v.y + sb1[hb + 2 * p + 1], 0.f);
                *reinterpret_cast<float2*>(&sH[(rb + e) * SH_PITCH + hb + 2 * p]) = v;
            }
        }
    }

    // ---- GEMM3: g_h = sX @ W_root + b_root (before barrier: absorbs skew) --
    {
        unsigned long long a3[4][2];
#pragma unroll
        for (int e = 0; e < 4; e++) { a3[e][0] = 0ULL; a3[e][1] = 0ULL; }

#pragma unroll 8
        for (int k = 0; k < C_IN; k += 2) {
            ulonglong2 wa = *reinterpret_cast<const ulonglong2*>(&sWr[k * C_OUT + kb]);
            ulonglong2 wb = *reinterpret_cast<const ulonglong2*>(&sWr[(k + 1) * C_OUT + kb]);
#pragma unroll
            for (int e = 0; e < 4; e++) {
                float2 xv = *reinterpret_cast<const float2*>(&sX[(rb + e) * SX_PITCH + k]);
                unsigned long long x0 = pack2(xv.x), x1 = pack2(xv.y);
                a3[e][0] = fma2(x0, wa.x, a3[e][0]);
                a3[e][1] = fma2(x0, wa.y, a3[e][1]);
                a3[e][0] = fma2(x1, wb.x, a3[e][0]);
                a3[e][1] = fma2(x1, wb.y, a3[e][1]);
            }
        }
        float c0 = sbr[kb], c1 = sbr[kb + 1], c2 = sbr[kb + 2], c3 = sbr[kb + 3];
#pragma unroll
        for (int e = 0; e < 4; e++) {
            int n = n0 + rb + e;
            if (n >= N) continue;
            float2 v0 = unpack2(a3[e][0]);
            float2 v1 = unpack2(a3[e][1]);
            float4 r;
            r.x = v0.x + c0; r.y = v0.y + c1; r.z = v1.x + c2; r.w = v1.y + c3;
            *reinterpret_cast<float4*>(&g_h[(long long)n * C_OUT + kb]) = r;
        }
    }
    __syncthreads();

    // ---- GEMM2: g_msg = sH @ W2 + b2 ----
    {
        unsigned long long a2[4][2];
#pragma unroll
        for (int e = 0; e < 4; e++) { a2[e][0] = 0ULL; a2[e][1] = 0ULL; }

#pragma unroll 8
        for (int j = 0; j < C_HID; j += 2) {
            ulonglong2 wa = *reinterpret_cast<const ulonglong2*>(&sW2[j * C_OUT + kb]);
            ulonglong2 wb = *reinterpret_cast<const ulonglong2*>(&sW2[(j + 1) * C_OUT + kb]);
#pragma unroll
            for (int e = 0; e < 4; e++) {
                float2 hv = *reinterpret_cast<const float2*>(&sH[(rb + e) * SH_PITCH + j]);
                unsigned long long h0 = pack2(hv.x), h1 = pack2(hv.y);
                a2[e][0] = fma2(h0, wa.x, a2[e][0]);
                a2[e][1] = fma2(h0, wa.y, a2[e][1]);
                a2[e][0] = fma2(h1, wb.x, a2[e][0]);
                a2[e][1] = fma2(h1, wb.y, a2[e][1]);
            }
        }
        float c0 = sb2[kb], c1 = sb2[kb + 1], c2 = sb2[kb + 2], c3 = sb2[kb + 3];
#pragma unroll
        for (int e = 0; e < 4; e++) {
            int n = n0 + rb + e;
            if (n >= N) continue;
            float2 v0 = unpack2(a2[e][0]);
            float2 v1 = unpack2(a2[e][1]);
            float4 r;
            r.x = v0.x + c0; r.y = v0.y + c1; r.z = v1.x + c2; r.w = v1.y + c3;
            *reinterpret_cast<float4*>(&g_msg[(long long)n * C_OUT + kb]) = r;
        }
    }
}

// ---------------------------------------------------------------------------
// K5: gather-aggregate + PReLU + BN-stats (16 threads per dst node).
//   h[n] = PReLU(g_h[n] + sum_{e in CSR[n]} msg[src_e])  (written in place)
//   stats accumulated per-channel (thread q owns channels 4q..4q+3).
// ---------------------------------------------------------------------------
__global__ __launch_bounds__(NT) void agg_kernel(const float* __restrict__ prelu_w,
                                                 int N) {
    const float a = prelu_w[0];
    const int q = threadIdx.x & 15;
    const int grp = blockIdx.x * (NT / 16) + (threadIdx.x >> 4);
    const int ngrp = gridDim.x * (NT / 16);

    float s0 = 0.f, s1 = 0.f, s2 = 0.f, s3 = 0.f;
    float q0 = 0.f, q1 = 0.f, q2 = 0.f, q3 = 0.f;

    for (int n = grp; n < N; n += ngrp) {
        int eb = __ldg(&g_off[n]);
        int ee = __ldg(&g_off[n + 1]);
        float4 acc = *reinterpret_cast<const float4*>(&g_h[(long long)n * C_OUT + q * 4]);
        for (int e = eb; e < ee; e++) {
            int src = __ldg(&g_esrc[e]);
            float4 m =
                *reinterpret_cast<const float4*>(&g_msg[(long long)src * C_OUT + q * 4]);
            acc.x += m.x; acc.y += m.y; acc.z += m.z; acc.w += m.w;
        }
        acc.x = (acc.x >= 0.f) ? acc.x : a * acc.x;
        acc.y = (acc.y >= 0.f) ? acc.y : a * acc.y;
        acc.z = (acc.z >= 0.f) ? acc.z : a * acc.z;
        acc.w = (acc.w >= 0.f) ? acc.w : a * acc.w;
        *reinterpret_cast<float4*>(&g_h[(long long)n * C_OUT + q * 4]) = acc;
        s0 += acc.x; s1 += acc.y; s2 += acc.z; s3 += acc.w;
        q0 += acc.x * acc.x; q1 += acc.y * acc.y;
        q2 += acc.z * acc.z; q3 += acc.w * acc.w;
    }

    __shared__ float rs[NT * 4], rq[NT * 4];
    int t = threadIdx.x;
    rs[t * 4 + 0] = s0; rs[t * 4 + 1] = s1; rs[t * 4 + 2] = s2; rs[t * 4 + 3] = s3;
    rq[t * 4 + 0] = q0; rq[t * 4 + 1] = q1; rq[t * 4 + 2] = q2; rq[t * 4 + 3] = q3;
    __syncthreads();
    if (t < 64) {
        int qq = t >> 2, comp = t & 3;
        float ts = 0.f, tq = 0.f;
#pragma unroll
        for (int m = 0; m < 16; m++) {
            int src = (m * 16 + qq) * 4 + comp;
            ts += rs[src];
            tq += rq[src];
        }
        atomicAdd(&g_stats[t], ts);
        atomicAdd(&g_stats[64 + t], tq);
    }
}

// ---------------------------------------------------------------------------
// K6: finalize BN (g_h already holds PReLU'd values) -> out
// ---------------------------------------------------------------------------
__global__ void bn_kernel(float* __restrict__ out, const float* __restrict__ gamma,
                          const float* __restrict__ beta, int N) {
    __shared__ float sscale[C_OUT], sshift[C_OUT];
    if (threadIdx.x < C_OUT) {
        float invN = 1.f / (float)N;
        float mu = g_stats[threadIdx.x] * invN;
        float var = g_stats[64 + threadIdx.x] * invN - mu * mu;
        float inv = rsqrtf(var + 1e-5f);
        float g = gamma[threadIdx.x] * inv;
        sscale[threadIdx.x] = g;
        sshift[threadIdx.x] = beta[threadIdx.x] - mu * g;
    }
    __syncthreads();
    const int total4 = N * (C_OUT / 4);
    const int stride = gridDim.x * blockDim.x;
    const float4* gh4 = reinterpret_cast<const float4*>(g_h);
    float4* o4 = reinterpret_cast<float4*>(out);
    for (int i = blockIdx.x * blockDim.x + threadIdx.x; i < total4; i += stride) {
        int q = (i & 15);
        float4 sc = reinterpret_cast<const float4*>(sscale)[q];
        float4 sh = reinterpret_cast<const float4*>(sshift)[q];
        float4 v = gh4[i];
        float4 r;
        r.x = fmaf(v.x, sc.x, sh.x);
        r.y = fmaf(v.y, sc.y, sh.y);
        r.z = fmaf(v.z, sc.z, sh.z);
        r.w = fmaf(v.w, sc.w, sh.w);
        o4[i] = r;
    }
}

// ---------------------------------------------------------------------------
extern "C" void kernel_launch(void* const* d_in, const int* in_sizes, int n_in,
                              void* d_out, int out_size) {
    const float* x = (const float*)d_in[0];
    const void* ei = d_in[1];
    const float* W1 = (const float*)d_in[2];
    const float* b1 = (const float*)d_in[3];
    const float* W2 = (const float*)d_in[4];
    const float* b2 = (const float*)d_in[5];
    const float* Wr = (const float*)d_in[6];
    const float* br = (const float*)d_in[7];
    const float* pw = (const float*)d_in[8];
    const float* gamma = (const float*)d_in[9];
    const float* beta = (const float*)d_in[10];
    float* out = (float*)d_out;

    const int N = in_sizes[0] / C_IN;
    const int E = in_sizes[1] / 2;
    const int nScanBlk = (N + SCAN_B - 1) / SCAN_B;

    cudaFuncSetAttribute(msg_kernel, cudaFuncAttributeMaxDynamicSharedMemorySize,
                         SMEM_BYTES);

    // sort chain (by dst)
    setup_kernel<<<64, 512>>>(ei, N);
    hist_kernel<<<(E + NT - 1) / NT, NT>>>(ei, E);
    scanA_kernel<<<nScanBlk, SCAN_B>>>(N);
    scanC_kernel<<<nScanBlk, SCAN_B>>>(N);
    reorder_kernel<<<(E + NT - 1) / NT, NT>>>(ei, E);

    // per-node MLP (msg) + root transform
    const int numTiles = (N + TILE_N - 1) / TILE_N;
    msg_kernel<<<numTiles, MT, SMEM_BYTES>>>(x, W1, b1, W2, b2, Wr, br, N);

    // gather-aggregate + PReLU + stats
    agg_kernel<<<592, NT>>>(pw, N);

    // BN finalize
    bn_kernel<<<592, NT>>>(out, gamma, beta, N);
}

// round 8
// speedup vs baseline: 1.1461x; 1.0658x over previous
#include <cuda_runtime.h>
#include <cstdint>

// ---------------------------------------------------------------------------
// GNBlock: h = BN(PReLU(segment_sum(relu(x[src]@W1+b1)@W2+b2, dst) + x@W_root + b_root))
// N=50000, E=800000, C_IN=64, C_HID=128, C_OUT=64
//
// msg = MLP(x[src]) is per-node -> compute once per node (persistent kernel).
// Aggregation by GATHER: counting-sort edges by dst (CSR, lean shfl scans),
// then each dst group reads msg rows and writes ONE row (no atomics).
// PReLU + BN-stats fused into the gather kernel.
// ---------------------------------------------------------------------------

#define N_MAX 50000
#define E_MAX 800000
#define C_IN 64
#define C_HID 128
#define C_OUT 64
#define TILE_N 128
#define MT 512
#define NT 256
#define SCAN_B 256

__device__ __align__(16) float g_h[N_MAX * C_OUT];    // root -> post-PReLU h
__device__ __align__(16) float g_msg[N_MAX * C_OUT];  // per-node messages
__device__ float g_stats[2 * C_OUT];
__device__ int g_idx64;
__device__ int g_cnt[N_MAX];
__device__ int g_off[N_MAX + 1];
__device__ int g_cursor[N_MAX];
__device__ int g_esrc[E_MAX];  // src list, CSR-ordered by dst
__device__ int g_part[SCAN_B];

// ---- f32x2 packed helpers ---------------------------------------------------
__device__ __forceinline__ unsigned long long pack2(float v) {
    unsigned long long r;
    unsigned int u = __float_as_uint(v);
    asm("mov.b64 %0, {%1, %2};" : "=l"(r) : "r"(u), "r"(u));
    return r;
}
__device__ __forceinline__ unsigned long long fma2(unsigned long long a,
                                                   unsigned long long b,
                                                   unsigned long long c) {
    unsigned long long d;
    asm("fma.rn.f32x2 %0, %1, %2, %3;" : "=l"(d) : "l"(a), "l"(b), "l"(c));
    return d;
}
__device__ __forceinline__ float2 unpack2(unsigned long long v) {
    unsigned int lo, hi;
    asm("mov.b64 {%0, %1}, %2;" : "=r"(lo), "=r"(hi) : "l"(v));
    float2 f;
    f.x = __uint_as_float(lo);
    f.y = __uint_as_float(hi);
    return f;
}

// ---------------------------------------------------------------------------
// K0: zero g_cnt/g_stats + detect index width
// ---------------------------------------------------------------------------
__global__ void setup_kernel(const void* __restrict__ ei, int N) {
    int gid = blockIdx.x * blockDim.x + threadIdx.x;
    int stride = gridDim.x * blockDim.x;
    for (int i = gid; i < N; i += stride) g_cnt[i] = 0;
    if (gid < 128) g_stats[gid] = 0.f;
    if (blockIdx.x == 0 && threadIdx.x < 32) {
        const long long* p = (const long long*)ei;
        long long v = p[threadIdx.x];
        unsigned ok = __ballot_sync(0xffffffffu, v >= 0 && v < (long long)N);
        if (threadIdx.x == 0) g_idx64 = (ok == 0xffffffffu) ? 1 : 0;
    }
}

// ---------------------------------------------------------------------------
// K1: histogram of dst (loads dst column only)
// ---------------------------------------------------------------------------
__global__ void hist_kernel(const void* __restrict__ ei, int E) {
    int e = blockIdx.x * blockDim.x + threadIdx.x;
    if (e >= E) return;
    int d;
    if (g_idx64) d = (int)__ldg(&((const long long*)ei)[E + e]);
    else d = __ldg(&((const int*)ei)[E + e]);
    atomicAdd(&g_cnt[d], 1);
}

// ---------------------------------------------------------------------------
// K2a: per-block partial sums of g_cnt (warp-shuffle reduce, 1 barrier)
// ---------------------------------------------------------------------------
__global__ void scanA_kernel(int N) {
    __shared__ int ws[8];
    int t = threadIdx.x;
    int lane = t & 31, wid = t >> 5;
    int i = blockIdx.x * SCAN_B + t;
    int v = (i < N) ? g_cnt[i] : 0;
#pragma unroll
    for (int o = 16; o > 0; o >>= 1) v += __shfl_down_sync(0xffffffffu, v, o);
    if (lane == 0) ws[wid] = v;
    __syncthreads();
    if (wid == 0) {
        int s = (lane < 8) ? ws[lane] : 0;
#pragma unroll
        for (int o = 4; o > 0; o >>= 1) s += __shfl_down_sync(0xffffffffu, s, o);
        if (lane == 0) g_part[blockIdx.x] = s;
    }
}

// ---------------------------------------------------------------------------
// K2b: per-block exclusive scan (shfl) + inline block prefix from g_part
// ---------------------------------------------------------------------------
__global__ void scanC_kernel(int N) {
    __shared__ int wsum[8];
    __shared__ int spref;
    int t = threadIdx.x;
    int lane = t & 31, wid = t >> 5;
    int b = blockIdx.x;
    int i = b * SCAN_B + t;
    int v = (i < N) ? g_cnt[i] : 0;
    int inc = v;
#pragma unroll
    for (int o = 1; o < 32; o <<= 1) {
        int u = __shfl_up_sync(0xffffffffu, inc, o);
        if (lane >= o) inc += u;
    }
    if (lane == 31) wsum[wid] = inc;
    __syncthreads();
    if (t == 0) {
        int acc = 0;
#pragma unroll
        for (int w = 0; w < 8; w++) {
            int xv = wsum[w];
            wsum[w] = acc;
            acc += xv;
        }
    }
    if (wid == 1) {  // warp 1: block prefix = sum g_part[0..b)
        int s = 0;
        for (int j = lane; j < b; j += 32) s += g_part[j];
#pragma unroll
        for (int o = 16; o > 0; o >>= 1) s += __shfl_down_sync(0xffffffffu, s, o);
        if (lane == 0) spref = s;
    }
    __syncthreads();
    int off = spref + wsum[wid] + inc - v;  // exclusive global
    if (i < N) {
        g_off[i] = off;
        g_cursor[i] = off;
        if (i == N - 1) g_off[N] = off + v;
    }
}

// ---------------------------------------------------------------------------
// K3: bucket edges by dst: g_esrc[pos] = src
// ---------------------------------------------------------------------------
__global__ void reorder_kernel(const void* __restrict__ ei, int E) {
    int e = blockIdx.x * blockDim.x + threadIdx.x;
    if (e >= E) return;
    int s, d;
    if (g_idx64) {
        const long long* p = (const long long*)ei;
        s = (int)__ldg(&p[e]);
        d = (int)__ldg(&p[E + e]);
    } else {
        const int* p = (const int*)ei;
        s = __ldg(&p[e]);
        d = __ldg(&p[E + e]);
    }
    int pos = atomicAdd(&g_cursor[d], 1);
    g_esrc[pos] = s;
}

// ---------------------------------------------------------------------------
// K4: PERSISTENT fused per-node kernel. Each block stages weights once, then
// loops over 128-node tiles:
//   msg[n] = relu(x[n]@W1 + b1) @ W2 + b2  -> g_msg
//   h[n]   = x[n]@W_root + b_root          -> g_h
// ---------------------------------------------------------------------------
#define SX_PITCH 68
#define SH_PITCH 132
#define SMEM_FLOATS (8192 + 8192 + 4096 + TILE_N * SX_PITCH + TILE_N * SH_PITCH + 256)
#define SMEM_BYTES (SMEM_FLOATS * 4)

__global__ __launch_bounds__(MT) void msg_kernel(
    const float* __restrict__ x, const float* __restrict__ W1,
    const float* __restrict__ b1, const float* __restrict__ W2,
    const float* __restrict__ b2, const float* __restrict__ Wr,
    const float* __restrict__ br, int N, int numTiles) {
    extern __shared__ float sm[];
    float* sW1 = sm;                      // 64 x 128
    float* sW2 = sW1 + 64 * 128;          // 128 x 64
    float* sWr = sW2 + 128 * 64;          // 64 x 64
    float* sX = sWr + 64 * 64;            // 128 x 68 (padded)
    float* sH = sX + TILE_N * SX_PITCH;   // 128 x 132 (padded)
    float* sb1 = sH + TILE_N * SH_PITCH;  // 128
    float* sb2 = sb1 + 128;               // 64
    float* sbr = sb2 + 64;                // 64

    const int tid = threadIdx.x;

    // stage weights + biases ONCE
    for (int i = tid; i < 2048; i += MT)
        reinterpret_cast<float4*>(sW1)[i] = reinterpret_cast<const float4*>(W1)[i];
    for (int i = tid; i < 2048; i += MT)
        reinterpret_cast<float4*>(sW2)[i] = reinterpret_cast<const float4*>(W2)[i];
    for (int i = tid; i < 1024; i += MT)
        reinterpret_cast<float4*>(sWr)[i] = reinterpret_cast<const float4*>(Wr)[i];
    if (tid < 128) sb1[tid] = b1[tid];
    else if (tid < 192) sb2[tid - 128] = b2[tid - 128];
    else if (tid < 256) sbr[tid - 192] = br[tid - 192];

    const int hg = tid & 15;
    const int rg = tid >> 4;
    const int hb = hg * 8;
    const int kb = hg * 4;
    const int rb = rg * 4;

    for (int tile = blockIdx.x; tile < numTiles; tile += gridDim.x) {
        const int n0 = tile * TILE_N;
        __syncthreads();  // previous tile's GEMM2 (sH readers) done; weights staged

        for (int i = tid; i < TILE_N * 16; i += MT) {
            int r = i >> 4, q = i & 15;
            int n = n0 + r;
            if (n >= N) n = N - 1;
            float4 v = reinterpret_cast<const float4*>(x + (long long)n * C_IN)[q];
            *reinterpret_cast<float4*>(&sX[r * SX_PITCH + q * 4]) = v;
        }
        __syncthreads();

        // ---- GEMM1: sH = relu(sX @ W1 + b1) ----
        {
            unsigned long long acc[4][4];
#pragma unroll
            for (int e = 0; e < 4; e++)
#pragma unroll
                for (int p = 0; p < 4; p++) acc[e][p] = 0ULL;

#pragma unroll 8
            for (int k = 0; k < C_IN; k += 2) {
                ulonglong2 wa0 = *reinterpret_cast<const ulonglong2*>(&sW1[k * C_HID + hb]);
                ulonglong2 wa1 =
                    *reinterpret_cast<const ulonglong2*>(&sW1[k * C_HID + hb + 4]);
                ulonglong2 wb0 =
                    *reinterpret_cast<const ulonglong2*>(&sW1[(k + 1) * C_HID + hb]);
                ulonglong2 wb1 =
                    *reinterpret_cast<const ulonglong2*>(&sW1[(k + 1) * C_HID + hb + 4]);
#pragma unroll
                for (int e = 0; e < 4; e++) {
                    float2 xv = *reinterpret_cast<const float2*>(&sX[(rb + e) * SX_PITCH + k]);
                    unsigned long long x0 = pack2(xv.x), x1 = pack2(xv.y);
                    acc[e][0] = fma2(x0, wa0.x, acc[e][0]);
                    acc[e][1] = fma2(x0, wa0.y, acc[e][1]);
                    acc[e][2] = fma2(x0, wa1.x, acc[e][2]);
                    acc[e][3] = fma2(x0, wa1.y, acc[e][3]);
                    acc[e][0] = fma2(x1, wb0.x, acc[e][0]);
                    acc[e][1] = fma2(x1, wb0.y, acc[e][1]);
                    acc[e][2] = fma2(x1, wb1.x, acc[e][2]);
                    acc[e][3] = fma2(x1, wb1.y, acc[e][3]);
                }
            }
#pragma unroll
            for (int e = 0; e < 4; e++) {
#pragma unroll
                for (int p = 0; p < 4; p++) {
                    float2 v = unpack2(acc[e][p]);
                    v.x = fmaxf(v.x + sb1[hb + 2 * p], 0.f);
                    v.y = fmaxf(v.y + sb1[hb + 2 * p + 1], 0.f);
                    *reinterpret_cast<float2*>(&sH[(rb + e) * SH_PITCH + hb + 2 * p]) = v;
                }
            }
        }

        // ---- GEMM3: g_h = sX @ W_root + b_root (before barrier) ----
        {
            unsigned long long a3[4][2];
#pragma unroll
            for (int e = 0; e < 4; e++) { a3[e][0] = 0ULL; a3[e][1] = 0ULL; }

#pragma unroll 8
            for (int k = 0; k < C_IN; k += 2) {
                ulonglong2 wa = *reinterpret_cast<const ulonglong2*>(&sWr[k * C_OUT + kb]);
                ulonglong2 wb =
                    *reinterpret_cast<const ulonglong2*>(&sWr[(k + 1) * C_OUT + kb]);
#pragma unroll
                for (int e = 0; e < 4; e++) {
                    float2 xv = *reinterpret_cast<const float2*>(&sX[(rb + e) * SX_PITCH + k]);
                    unsigned long long x0 = pack2(xv.x), x1 = pack2(xv.y);
                    a3[e][0] = fma2(x0, wa.x, a3[e][0]);
                    a3[e][1] = fma2(x0, wa.y, a3[e][1]);
                    a3[e][0] = fma2(x1, wb.x, a3[e][0]);
                    a3[e][1] = fma2(x1, wb.y, a3[e][1]);
                }
            }
            float c0 = sbr[kb], c1 = sbr[kb + 1], c2 = sbr[kb + 2], c3 = sbr[kb + 3];
#pragma unroll
            for (int e = 0; e < 4; e++) {
                int n = n0 + rb + e;
                if (n >= N) continue;
                float2 v0 = unpack2(a3[e][0]);
                float2 v1 = unpack2(a3[e][1]);
                float4 r;
                r.x = v0.x + c0; r.y = v0.y + c1; r.z = v1.x + c2; r.w = v1.y + c3;
                *reinterpret_cast<float4*>(&g_h[(long long)n * C_OUT + kb]) = r;
            }
        }
        __syncthreads();

        // ---- GEMM2: g_msg = sH @ W2 + b2 ----
        {
            unsigned long long a2[4][2];
#pragma unroll
            for (int e = 0; e < 4; e++) { a2[e][0] = 0ULL; a2[e][1] = 0ULL; }

#pragma unroll 8
            for (int j = 0; j < C_HID; j += 2) {
                ulonglong2 wa = *reinterpret_cast<const ulonglong2*>(&sW2[j * C_OUT + kb]);
                ulonglong2 wb =
                    *reinterpret_cast<const ulonglong2*>(&sW2[(j + 1) * C_OUT + kb]);
#pragma unroll
                for (int e = 0; e < 4; e++) {
                    float2 hv = *reinterpret_cast<const float2*>(&sH[(rb + e) * SH_PITCH + j]);
                    unsigned long long h0 = pack2(hv.x), h1 = pack2(hv.y);
                    a2[e][0] = fma2(h0, wa.x, a2[e][0]);
                    a2[e][1] = fma2(h0, wa.y, a2[e][1]);
                    a2[e][0] = fma2(h1, wb.x, a2[e][0]);
                    a2[e][1] = fma2(h1, wb.y, a2[e][1]);
                }
            }
            float c0 = sb2[kb], c1 = sb2[kb + 1], c2 = sb2[kb + 2], c3 = sb2[kb + 3];
#pragma unroll
            for (int e = 0; e < 4; e++) {
                int n = n0 + rb + e;
                if (n >= N) continue;
                float2 v0 = unpack2(a2[e][0]);
                float2 v1 = unpack2(a2[e][1]);
                float4 r;
                r.x = v0.x + c0; r.y = v0.y + c1; r.z = v1.x + c2; r.w = v1.y + c3;
                *reinterpret_cast<float4*>(&g_msg[(long long)n * C_OUT + kb]) = r;
            }
        }
    }
}

// ---------------------------------------------------------------------------
// K5: gather-aggregate + PReLU + BN-stats (16 threads per dst node).
//   h[n] = PReLU(g_h[n] + sum_{e in CSR[n]} msg[src_e])  (in place)
// Edge loop unrolled x2 for memory-level parallelism.
// ---------------------------------------------------------------------------
__global__ __launch_bounds__(NT) void agg_kernel(const float* __restrict__ prelu_w,
                                                 int N) {
    const float a = prelu_w[0];
    const int q = threadIdx.x & 15;
    const int grp = blockIdx.x * (NT / 16) + (threadIdx.x >> 4);
    const int ngrp = gridDim.x * (NT / 16);

    float s0 = 0.f, s1 = 0.f, s2 = 0.f, s3 = 0.f;
    float q0 = 0.f, q1 = 0.f, q2 = 0.f, q3 = 0.f;

    for (int n = grp; n < N; n += ngrp) {
        int eb = __ldg(&g_off[n]);
        int ee = __ldg(&g_off[n + 1]);
        float4 acc = *reinterpret_cast<const float4*>(&g_h[(long long)n * C_OUT + q * 4]);
        int e = eb;
        for (; e + 1 < ee; e += 2) {
            int sa = __ldg(&g_esrc[e]);
            int sb = __ldg(&g_esrc[e + 1]);
            float4 m0 =
                *reinterpret_cast<const float4*>(&g_msg[(long long)sa * C_OUT + q * 4]);
            float4 m1 =
                *reinterpret_cast<const float4*>(&g_msg[(long long)sb * C_OUT + q * 4]);
            acc.x += m0.x; acc.y += m0.y; acc.z += m0.z; acc.w += m0.w;
            acc.x += m1.x; acc.y += m1.y; acc.z += m1.z; acc.w += m1.w;
        }
        if (e < ee) {
            int sa = __ldg(&g_esrc[e]);
            float4 m0 =
                *reinterpret_cast<const float4*>(&g_msg[(long long)sa * C_OUT + q * 4]);
            acc.x += m0.x; acc.y += m0.y; acc.z += m0.z; acc.w += m0.w;
        }
        acc.x = (acc.x >= 0.f) ? acc.x : a * acc.x;
        acc.y = (acc.y >= 0.f) ? acc.y : a * acc.y;
        acc.z = (acc.z >= 0.f) ? acc.z : a * acc.z;
        acc.w = (acc.w >= 0.f) ? acc.w : a * acc.w;
        *reinterpret_cast<float4*>(&g_h[(long long)n * C_OUT + q * 4]) = acc;
        s0 += acc.x; s1 += acc.y; s2 += acc.z; s3 += acc.w;
        q0 += acc.x * acc.x; q1 += acc.y * acc.y;
        q2 += acc.z * acc.z; q3 += acc.w * acc.w;
    }

    __shared__ float rs[NT * 4], rq[NT * 4];
    int t = threadIdx.x;
    rs[t * 4 + 0] = s0; rs[t * 4 + 1] = s1; rs[t * 4 + 2] = s2; rs[t * 4 + 3] = s3;
    rq[t * 4 + 0] = q0; rq[t * 4 + 1] = q1; rq[t * 4 + 2] = q2; rq[t * 4 + 3] = q3;
    __syncthreads();
    if (t < 64) {
        int qq = t >> 2, comp = t & 3;
        float ts = 0.f, tq = 0.f;
#pragma unroll
        for (int m = 0; m < 16; m++) {
            int src = (m * 16 + qq) * 4 + comp;
            ts += rs[src];
            tq += rq[src];
        }
        atomicAdd(&g_stats[t], ts);
        atomicAdd(&g_stats[64 + t], tq);
    }
}

// ---------------------------------------------------------------------------
// K6: finalize BN (g_h already holds PReLU'd values) -> out
// ---------------------------------------------------------------------------
__global__ void bn_kernel(float* __restrict__ out, const float* __restrict__ gamma,
                          const float* __restrict__ beta, int N) {
    __shared__ float sscale[C_OUT], sshift[C_OUT];
    if (threadIdx.x < C_OUT) {
        float invN = 1.f / (float)N;
        float mu = g_stats[threadIdx.x] * invN;
        float var = g_stats[64 + threadIdx.x] * invN - mu * mu;
        float inv = rsqrtf(var + 1e-5f);
        float g = gamma[threadIdx.x] * inv;
        sscale[threadIdx.x] = g;
        sshift[threadIdx.x] = beta[threadIdx.x] - mu * g;
    }
    __syncthreads();
    const int total4 = N * (C_OUT / 4);
    const int stride = gridDim.x * blockDim.x;
    const float4* gh4 = reinterpret_cast<const float4*>(g_h);
    float4* o4 = reinterpret_cast<float4*>(out);
    for (int i = blockIdx.x * blockDim.x + threadIdx.x; i < total4; i += stride) {
        int q = (i & 15);
        float4 sc = reinterpret_cast<const float4*>(sscale)[q];
        float4 sh = reinterpret_cast<const float4*>(sshift)[q];
        float4 v = gh4[i];
        float4 r;
        r.x = fmaf(v.x, sc.x, sh.x);
        r.y = fmaf(v.y, sc.y, sh.y);
        r.z = fmaf(v.z, sc.z, sh.z);
        r.w = fmaf(v.w, sc.w, sh.w);
        o4[i] = r;
    }
}

// ---------------------------------------------------------------------------
extern "C" void kernel_launch(void* const* d_in, const int* in_sizes, int n_in,
                              void* d_out, int out_size) {
    const float* x = (const float*)d_in[0];
    const void* ei = d_in[1];
    const float* W1 = (const float*)d_in[2];
    const float* b1 = (const float*)d_in[3];
    const float* W2 = (const float*)d_in[4];
    const float* b2 = (const float*)d_in[5];
    const float* Wr = (const float*)d_in[6];
    const float* br = (const float*)d_in[7];
    const float* pw = (const float*)d_in[8];
    const float* gamma = (const float*)d_in[9];
    const float* beta = (const float*)d_in[10];
    float* out = (float*)d_out;

    const int N = in_sizes[0] / C_IN;
    const int E = in_sizes[1] / 2;
    const int nScanBlk = (N + SCAN_B - 1) / SCAN_B;
    const int numTiles = (N + TILE_N - 1) / TILE_N;

    static int nSM = 0;
    if (nSM == 0) cudaDeviceGetAttribute(&nSM, cudaDevAttrMultiProcessorCount, 0);

    cudaFuncSetAttribute(msg_kernel, cudaFuncAttributeMaxDynamicSharedMemorySize,
                         SMEM_BYTES);

    // sort chain (by dst)
    setup_kernel<<<128, 512>>>(ei, N);
    hist_kernel<<<(E + 511) / 512, 512>>>(ei, E);
    scanA_kernel<<<nScanBlk, SCAN_B>>>(N);
    scanC_kernel<<<nScanBlk, SCAN_B>>>(N);
    reorder_kernel<<<(E + 511) / 512, 512>>>(ei, E);

    // persistent per-node MLP (msg) + root transform
    msg_kernel<<<nSM, MT, SMEM_BYTES>>>(x, W1, b1, W2, b2, Wr, br, N, numTiles);

    // gather-aggregate + PReLU + stats
    agg_kernel<<<592, NT>>>(pw, N);

    // BN finalize
    bn_kernel<<<592, NT>>>(out, gamma, beta, N);
}